// round 14
// baseline (speedup 1.0000x reference)
#include <cuda_runtime.h>
#include <cuda_bf16.h>
#include <math.h>
#include <stdint.h>

#define TT 65536
#define BB 64
#define XX 512
#define HH 512
#define YY 2560

// -------- scratch (device globals; no allocation allowed) --------
__device__ float g_cpart[10][BB * HH];
__device__ float g_c[BB * HH];
__device__ __nv_bfloat16 g_H1b[(size_t)TT * HH];
__device__ __nv_bfloat16 g_WT1b[HH * HH];   // W1[:512] transposed [n][k], bf16
__device__ __nv_bfloat16 g_WT2b[HH * HH];   // W2 transposed [n][k], bf16
__device__ float g_part[4 * TT];
__device__ float g_logits[TT];
__device__ float g_pooled[BB * XX];

// ==================== PTX helpers ====================
__device__ __forceinline__ uint32_t smem_u32(const void* p) {
    uint32_t a;
    asm("{ .reg .u64 t; cvta.to.shared.u64 t, %1; cvt.u32.u64 %0, t; }"
        : "=r"(a) : "l"(p));
    return a;
}
#define CP16(dst, src) \
    asm volatile("cp.async.cg.shared.global [%0], [%1], 16;" :: "r"(dst), "l"(src))
#define CPCOMMIT() asm volatile("cp.async.commit_group;" ::: "memory")
#define CPWAIT0()  asm volatile("cp.async.wait_group 0;" ::: "memory")
#define CPWAIT1()  asm volatile("cp.async.wait_group 1;" ::: "memory")

#define LDSM4(r, addr) \
    asm volatile("ldmatrix.sync.aligned.m8n8.x4.shared.b16 {%0,%1,%2,%3}, [%4];" \
        : "=r"((r)[0]), "=r"((r)[1]), "=r"((r)[2]), "=r"((r)[3]) : "r"(addr))

#define MMA_BF16(d, a, b) \
    asm volatile("mma.sync.aligned.m16n8k16.row.col.f32.bf16.bf16.f32 " \
        "{%0,%1,%2,%3}, {%4,%5,%6,%7}, {%8,%9}, {%0,%1,%2,%3};" \
        : "+f"((d)[0]), "+f"((d)[1]), "+f"((d)[2]), "+f"((d)[3]) \
        : "r"((a)[0]), "r"((a)[1]), "r"((a)[2]), "r"((a)[3]), \
          "r"((b)[0]), "r"((b)[1]))

// ====================================================================
// K0: WT[n][k] = bf16(W[k][n]).  grid (16,16,2): z selects W1a / W2.
// ====================================================================
__global__ void k_wt2(const float* __restrict__ W1, const float* __restrict__ W2) {
    __shared__ float t[32][33];
    const float* W = (blockIdx.z == 0) ? W1 : W2;
    __nv_bfloat16* WT = (blockIdx.z == 0) ? g_WT1b : g_WT2b;
    int bx = blockIdx.x * 32, by = blockIdx.y * 32;
    int x = threadIdx.x, y = threadIdx.y;         // (32, 8)
#pragma unroll
    for (int i = 0; i < 32; i += 8)
        t[y + i][x] = W[(size_t)(by + y + i) * HH + bx + x];
    __syncthreads();
#pragma unroll
    for (int i = 0; i < 32; i += 8)
        WT[(size_t)(bx + y + i) * HH + by + x] = __float2bfloat16(t[x][y + i]);
}

// ====================================================================
// K1a: partial c over 256-wide y-slice, 8 accumulator chains.
// grid (64, 10), 512 threads.  K1b: c = b1 + sum of 10 partials.
// ====================================================================
__global__ void k_compute_c_part(const float* __restrict__ io,
                                 const float* __restrict__ W1) {
    int b = blockIdx.x, s = blockIdx.y;
    int h = threadIdx.x;
    const float* e = io + b * YY + s * 256;
    const float* w = W1 + (size_t)(XX + s * 256) * HH + h;
    float a0 = 0.f, a1 = 0.f, a2 = 0.f, a3 = 0.f;
    float a4 = 0.f, a5 = 0.f, a6 = 0.f, a7 = 0.f;
#pragma unroll 4
    for (int y = 0; y < 256; y += 8) {
        a0 = fmaf(e[y],     w[(size_t)(y)     * HH], a0);
        a1 = fmaf(e[y + 1], w[(size_t)(y + 1) * HH], a1);
        a2 = fmaf(e[y + 2], w[(size_t)(y + 2) * HH], a2);
        a3 = fmaf(e[y + 3], w[(size_t)(y + 3) * HH], a3);
        a4 = fmaf(e[y + 4], w[(size_t)(y + 4) * HH], a4);
        a5 = fmaf(e[y + 5], w[(size_t)(y + 5) * HH], a5);
        a6 = fmaf(e[y + 6], w[(size_t)(y + 6) * HH], a6);
        a7 = fmaf(e[y + 7], w[(size_t)(y + 7) * HH], a7);
    }
    g_cpart[s][b * HH + h] = ((a0 + a1) + (a2 + a3)) + ((a4 + a5) + (a6 + a7));
}
__global__ void k_compute_c_red(const float* __restrict__ b1) {
    int i = blockIdx.x * 512 + threadIdx.x;
    float s = b1[threadIdx.x];
#pragma unroll
    for (int p = 0; p < 10; p++) s += g_cpart[p][i];
    g_c[i] = s;
}

// ====================================================================
// Persistent bf16 mma.sync GEMM: grid (4 nblk, 128), each CTA sweeps
// 4 m-tiles as one 64-step pipeline (prologue paid once; epilogues
// overlap with next tile's cp.async prefetch).  Block 128x128, BK=32,
// 8 warps, warp tile 64x32, 3 stages (wait_group 1), 2 CTA/SM.
// x-major CTA order: the 4 concurrent n-CTAs share A rows (L2 reuse).
// MODE 0: A = ps f32 (LDG+cvt+STS); out H1b = bf16(relu(D + c[seg])).
// MODE 1: A = H1b bf16 (cp.async); out g_part[nblk] per-row partial.
// ====================================================================
#define ABYT 10240                    // 128*40*2 per stage (A or B)
#define STG  20480                    // stage stride (A+B)
#define SM_DYN (3 * STG)              // 61440
#define NSTEP 64                      // 4 m-tiles x 16 k-tiles

template <int MODE>
__global__ __launch_bounds__(256, 2)
void k_gemm(const float* __restrict__ Af,          // MODE 0 source (f32)
            const __nv_bfloat16* __restrict__ Ab,  // MODE 1 source (bf16)
            const __nv_bfloat16* __restrict__ WT,  // [n][k] bf16
            const int*   __restrict__ seg,         // MODE 0
            const float* __restrict__ b2,          // MODE 1
            const float* __restrict__ W3) {        // MODE 1
    extern __shared__ char sm[];
    __shared__ float s_red[4][128];
    __shared__ float s_b2[128], s_w3[128];

    const int tid  = threadIdx.x;
    const int wid  = tid >> 5, lane = tid & 31;
    const int g    = lane >> 2, tg = lane & 3;
    const int wm   = (wid >> 2) * 64;             // 0 / 64
    const int wn   = (wid & 3) * 32;              // 0..96
    const int col0 = blockIdx.x * 128;
    const uint32_t sb = smem_u32(sm);

    if (MODE == 1 && tid < 128) { s_b2[tid] = b2[col0 + tid]; s_w3[tid] = W3[col0 + tid]; }

    float acc[4][4][4];
#pragma unroll
    for (int mi = 0; mi < 4; mi++)
#pragma unroll
        for (int ni = 0; ni < 4; ni++)
#pragma unroll
            for (int q = 0; q < 4; q++) acc[mi][ni][q] = 0.f;

    // ldmatrix lane address components
    const int a_row = (lane & 7) + ((lane >> 3) & 1) * 8;
    const int a_kh  = (lane >> 4) & 1;
    const int b_n   = (lane & 7) + ((lane >> 4) & 1) * 8;
    const int b_kh  = (lane >> 3) & 1;

    float4 pa[4];                                  // MODE 0 A staging (one stage ahead)

    // step -> (m-tile, k-tile):  row0(step) = ((step>>4)*128 + blockIdx.y)*128
#define ROW0(step) ((((step) >> 4) * 128 + blockIdx.y) * 128)

#define CP_ISSUE(step, st) do { \
    const int kts = (step) & 15; \
    const int r0s = ROW0(step); \
    const uint32_t bbp = sb + (st) * STG + ABYT; \
    _Pragma("unroll") \
    for (int j = 0; j < 2; j++) { \
        int c = tid + j * 256, n = c >> 2, part = c & 3; \
        CP16(bbp + n * 80 + part * 16, \
             WT + (size_t)(col0 + n) * 512 + kts * 32 + part * 8); \
    } \
    if (MODE == 1) { \
        const uint32_t abp = sb + (st) * STG; \
        _Pragma("unroll") \
        for (int j = 0; j < 2; j++) { \
            int c = tid + j * 256, r = c >> 2, part = c & 3; \
            CP16(abp + r * 80 + part * 16, \
                 Ab + (size_t)(r0s + r) * 512 + kts * 32 + part * 8); \
        } \
    } } while (0)

#define A_LDG(step) do { \
    const int kts = (step) & 15; \
    const int r0s = ROW0(step); \
    _Pragma("unroll") \
    for (int j = 0; j < 4; j++) { \
        int c = tid + j * 256, r = c >> 3, part = c & 7; \
        pa[j] = *(const float4*)(Af + (size_t)(r0s + r) * 512 + kts * 32 + part * 4); \
    } } while (0)

#define A_STS(st) do { \
    const uint32_t abp = sb + (st) * STG; \
    _Pragma("unroll") \
    for (int j = 0; j < 4; j++) { \
        int c = tid + j * 256, r = c >> 3, part = c & 7; \
        __nv_bfloat162 lo = __float22bfloat162_rn(make_float2(pa[j].x, pa[j].y)); \
        __nv_bfloat162 hi = __float22bfloat162_rn(make_float2(pa[j].z, pa[j].w)); \
        uint32_t ulo = *(uint32_t*)&lo, uhi = *(uint32_t*)&hi; \
        asm volatile("st.shared.v2.u32 [%0], {%1, %2};" \
            :: "r"(abp + r * 80 + part * 8), "r"(ulo), "r"(uhi)); \
    } } while (0)

    // ---- prologue: stages for steps 0 and 1 in flight ----
    CP_ISSUE(0, 0); CPCOMMIT();
    CP_ISSUE(1, 1); CPCOMMIT();
    if (MODE == 0) {
        A_LDG(0); A_STS(0);
        A_LDG(1); A_STS(1);
        A_LDG(2);                       // pa holds step-2 data
    }

    for (int step = 0; step < NSTEP; step++) {
        const int buf = step % 3;
        const int nxt = (step + 2) % 3;
        if (step >= NSTEP - 2) { CPWAIT0(); } else { CPWAIT1(); }
        __syncthreads();
        if (step < NSTEP - 2) {
            CP_ISSUE(step + 2, nxt);
            CPCOMMIT();
            if (MODE == 0) {
                A_STS(nxt);             // pa = step+2
                if (step < NSTEP - 3) A_LDG(step + 3);
            }
        }
        const uint32_t ab = sb + buf * STG;
        const uint32_t bb = ab + ABYT;
#pragma unroll
        for (int ks = 0; ks < 2; ks++) {
            uint32_t af[4][4], bf[4][2];
#pragma unroll
            for (int mi = 0; mi < 4; mi++)
                LDSM4(af[mi], ab + (wm + mi * 16 + a_row) * 80 + ks * 32 + a_kh * 16);
#pragma unroll
            for (int p = 0; p < 2; p++) {
                uint32_t r4[4];
                LDSM4(r4, bb + (wn + p * 16 + b_n) * 80 + ks * 32 + b_kh * 16);
                bf[2 * p][0] = r4[0]; bf[2 * p][1] = r4[1];
                bf[2 * p + 1][0] = r4[2]; bf[2 * p + 1][1] = r4[3];
            }
#pragma unroll
            for (int mi = 0; mi < 4; mi++)
#pragma unroll
                for (int ni = 0; ni < 4; ni++)
                    MMA_BF16(acc[mi][ni], af[mi], bf[ni]);
        }

        // -------- per-m-tile epilogue (overlaps next tile's cp.async) --------
        if ((step & 15) == 15) {
            const int row0 = ROW0(step);
            if (MODE == 0) {
#pragma unroll
                for (int mi = 0; mi < 4; mi++) {
#pragma unroll
                    for (int h = 0; h < 2; h++) {
                        int r = row0 + wm + mi * 16 + g + h * 8;
                        const float* crow = g_c + (size_t)__ldg(seg + r) * 512;
                        __nv_bfloat16* orow = g_H1b + (size_t)r * 512;
#pragma unroll
                        for (int ni = 0; ni < 4; ni++) {
                            int col = col0 + wn + ni * 8 + 2 * tg;
                            float x0 = fmaxf(acc[mi][ni][h * 2 + 0] + crow[col], 0.f);
                            float x1 = fmaxf(acc[mi][ni][h * 2 + 1] + crow[col + 1], 0.f);
                            __nv_bfloat162 o = __float22bfloat162_rn(make_float2(x0, x1));
                            *(__nv_bfloat162*)(orow + col) = o;
                        }
                    }
                }
            } else {
                float rp[4][2];
#pragma unroll
                for (int mi = 0; mi < 4; mi++) {
#pragma unroll
                    for (int h = 0; h < 2; h++) {
                        float s = 0.f;
#pragma unroll
                        for (int ni = 0; ni < 4; ni++) {
                            int cl = wn + ni * 8 + 2 * tg;
                            s = fmaf(fmaxf(acc[mi][ni][h * 2 + 0] + s_b2[cl], 0.f), s_w3[cl], s);
                            s = fmaf(fmaxf(acc[mi][ni][h * 2 + 1] + s_b2[cl + 1], 0.f), s_w3[cl + 1], s);
                        }
                        s += __shfl_xor_sync(0xffffffffu, s, 1);
                        s += __shfl_xor_sync(0xffffffffu, s, 2);
                        rp[mi][h] = s;
                    }
                }
                __syncthreads();
                if (tg == 0) {
#pragma unroll
                    for (int mi = 0; mi < 4; mi++)
#pragma unroll
                        for (int h = 0; h < 2; h++)
                            s_red[wid & 3][wm + mi * 16 + g + h * 8] = rp[mi][h];
                }
                __syncthreads();
                if (tid < 128) {
                    float v = (s_red[0][tid] + s_red[1][tid]) + (s_red[2][tid] + s_red[3][tid]);
                    g_part[(size_t)blockIdx.x * TT + row0 + tid] = v;
                }
            }
            // reset accumulators for next m-tile
#pragma unroll
            for (int mi = 0; mi < 4; mi++)
#pragma unroll
                for (int ni = 0; ni < 4; ni++)
#pragma unroll
                    for (int q = 0; q < 4; q++) acc[mi][ni][q] = 0.f;
        }
    }
#undef CP_ISSUE
#undef A_LDG
#undef A_STS
#undef ROW0
}

// ====================================================================
// K5: per-segment softmax + pooling.  64 blocks x 512 threads.
// Pass 1 builds logits from the 4 g_part slices (k_logit_red folded in;
// pass 2/3 use the same tid mapping, so each thread reads its own writes).
// ====================================================================
__global__ void k_seg_pool(const int* __restrict__ seg,
                           const float* __restrict__ ps,
                           const float* __restrict__ b3) {
    __shared__ float sbuf[512];
    __shared__ float s_mx, s_dn;
    const int b   = blockIdx.x;
    const int tid = threadIdx.x;

    int lo = 0, hi = TT;
    while (lo < hi) { int mid = (lo + hi) >> 1; if (seg[mid] < b) lo = mid + 1; else hi = mid; }
    const int start = lo;
    hi = TT;
    while (lo < hi) { int mid = (lo + hi) >> 1; if (seg[mid] < b + 1) lo = mid + 1; else hi = mid; }
    const int end = lo;

    const float b3v = b3[0];
    float m = -1e30f;
    for (int t = start + tid; t < end; t += 512) {
        float l = ((g_part[t] + g_part[TT + t])
                 + (g_part[2 * TT + t] + g_part[3 * TT + t])) + b3v;
        g_logits[t] = l;
        m = fmaxf(m, l);
    }
    sbuf[tid] = m; __syncthreads();
    for (int s = 256; s > 0; s >>= 1) {
        if (tid < s) sbuf[tid] = fmaxf(sbuf[tid], sbuf[tid + s]);
        __syncthreads();
    }
    if (tid == 0) s_mx = sbuf[0];
    __syncthreads();
    const float mx = s_mx;

    float sm = 0.f;
    for (int t = start + tid; t < end; t += 512) sm += expf(g_logits[t] - mx);
    __syncthreads();
    sbuf[tid] = sm; __syncthreads();
    for (int s = 256; s > 0; s >>= 1) {
        if (tid < s) sbuf[tid] += sbuf[tid + s];
        __syncthreads();
    }
    if (tid == 0) s_dn = sbuf[0];
    __syncthreads();
    const float inv = (end > start) ? 1.f / s_dn : 0.f;

    float a0 = 0.f, a1 = 0.f, a2 = 0.f, a3 = 0.f;
    float a4 = 0.f, a5 = 0.f, a6 = 0.f, a7 = 0.f;
    for (int c0 = start; c0 < end; c0 += 512) {
        int nt = min(512, end - c0);
        __syncthreads();
        if (tid < nt) sbuf[tid] = expf(g_logits[c0 + tid] - mx);
        __syncthreads();
        const float* prow = ps + (size_t)c0 * XX + tid;
        int i = 0;
        for (; i + 7 < nt; i += 8) {
            a0 = fmaf(sbuf[i],     prow[(size_t)(i)     * XX], a0);
            a1 = fmaf(sbuf[i + 1], prow[(size_t)(i + 1) * XX], a1);
            a2 = fmaf(sbuf[i + 2], prow[(size_t)(i + 2) * XX], a2);
            a3 = fmaf(sbuf[i + 3], prow[(size_t)(i + 3) * XX], a3);
            a4 = fmaf(sbuf[i + 4], prow[(size_t)(i + 4) * XX], a4);
            a5 = fmaf(sbuf[i + 5], prow[(size_t)(i + 5) * XX], a5);
            a6 = fmaf(sbuf[i + 6], prow[(size_t)(i + 6) * XX], a6);
            a7 = fmaf(sbuf[i + 7], prow[(size_t)(i + 7) * XX], a7);
        }
        for (; i < nt; i++)
            a0 = fmaf(sbuf[i], prow[(size_t)i * XX], a0);
    }
    g_pooled[(size_t)b * XX + tid] =
        (((a0 + a1) + (a2 + a3)) + ((a4 + a5) + (a6 + a7))) * inv;
}

// ====================================================================
// K6: out[b] = relu(pooled[b] @ Wf1 + bf1) @ Wf2 + bf2   (exact fp32)
// ====================================================================
__global__ void k_final(const float* __restrict__ Wf1,
                        const float* __restrict__ bf1,
                        const float* __restrict__ Wf2,
                        const float* __restrict__ bf2,
                        float* __restrict__ out) {
    __shared__ float p[512];
    __shared__ float hf[512];
    const int b = blockIdx.x;
    const int tid = threadIdx.x;

    p[tid] = g_pooled[b * XX + tid];
    __syncthreads();

    float acc = bf1[tid];
#pragma unroll 4
    for (int k = 0; k < 512; k++)
        acc = fmaf(p[k], Wf1[(size_t)k * 512 + tid], acc);
    hf[tid] = fmaxf(acc, 0.f);
    __syncthreads();

    float v0 = hf[tid] * Wf2[tid * 2 + 0];
    float v1 = hf[tid] * Wf2[tid * 2 + 1];
    __syncthreads();
    p[tid] = v0; __syncthreads();
    for (int s = 256; s > 0; s >>= 1) { if (tid < s) p[tid] += p[tid + s]; __syncthreads(); }
    if (tid == 0) out[b * 2 + 0] = p[0] + bf2[0];
    __syncthreads();
    p[tid] = v1; __syncthreads();
    for (int s = 256; s > 0; s >>= 1) { if (tid < s) p[tid] += p[tid + s]; __syncthreads(); }
    if (tid == 0) out[b * 2 + 1] = p[0] + bf2[1];
}

// ====================================================================
extern "C" void kernel_launch(void* const* d_in, const int* in_sizes, int n_in,
                              void* d_out, int out_size) {
    const float* ps  = (const float*)d_in[0];
    const float* io  = (const float*)d_in[1];
    const int*   seg = (const int*)  d_in[2];
    const float* W1  = (const float*)d_in[3];
    const float* b1  = (const float*)d_in[4];
    const float* W2  = (const float*)d_in[5];
    const float* b2  = (const float*)d_in[6];
    const float* W3  = (const float*)d_in[7];
    const float* b3  = (const float*)d_in[8];
    const float* Wf1 = (const float*)d_in[9];
    const float* bf1 = (const float*)d_in[10];
    const float* Wf2 = (const float*)d_in[11];
    const float* bf2 = (const float*)d_in[12];
    float* out = (float*)d_out;

    __nv_bfloat16 *H1b, *WT1b, *WT2b;
    cudaGetSymbolAddress((void**)&H1b,  g_H1b);
    cudaGetSymbolAddress((void**)&WT1b, g_WT1b);
    cudaGetSymbolAddress((void**)&WT2b, g_WT2b);

    cudaFuncSetAttribute(k_gemm<0>, cudaFuncAttributeMaxDynamicSharedMemorySize, SM_DYN);
    cudaFuncSetAttribute(k_gemm<1>, cudaFuncAttributeMaxDynamicSharedMemorySize, SM_DYN);

    k_wt2<<<dim3(16, 16, 2), dim3(32, 8)>>>(W1, W2);
    k_compute_c_part<<<dim3(BB, 10), 512>>>(io, W1);
    k_compute_c_red<<<BB, 512>>>(b1);

    // H1 = bf16(relu(ps @ W1a + c[seg]))  — persistent 4-m-tile sweep
    k_gemm<0><<<dim3(4, 128), 256, SM_DYN>>>(ps, nullptr, WT1b, seg, nullptr, nullptr);
    // logit partials = relu(H1 @ W2 + b2) . W3 per 128-col block
    k_gemm<1><<<dim3(4, 128), 256, SM_DYN>>>(nullptr, H1b, WT2b, nullptr, b2, W3);

    k_seg_pool<<<BB, 512>>>(seg, ps, b3);
    k_final<<<BB, 512>>>(Wf1, bf1, Wf2, bf2, out);
}

// round 16
// speedup vs baseline: 1.1088x; 1.1088x over previous
#include <cuda_runtime.h>
#include <cuda_bf16.h>
#include <math.h>
#include <stdint.h>

#define TT 65536
#define BB 64
#define XX 512
#define HH 512
#define YY 2560

// -------- scratch (device globals; no allocation allowed) --------
__device__ float g_cpart[10][BB * HH];
__device__ float g_c[BB * HH];
__device__ __nv_bfloat16 g_H1b[(size_t)TT * HH];
__device__ __nv_bfloat16 g_WT1b[HH * HH];   // W1[:512] transposed [n][k], bf16
__device__ __nv_bfloat16 g_WT2b[HH * HH];   // W2 transposed [n][k], bf16
__device__ float g_part[4 * TT];
__device__ float g_logits[TT];
__device__ float g_pooled[BB * XX];

// ==================== PTX helpers ====================
__device__ __forceinline__ uint32_t smem_u32(const void* p) {
    uint32_t a;
    asm("{ .reg .u64 t; cvta.to.shared.u64 t, %1; cvt.u32.u64 %0, t; }"
        : "=r"(a) : "l"(p));
    return a;
}
#define CP16(dst, src) \
    asm volatile("cp.async.cg.shared.global [%0], [%1], 16;" :: "r"(dst), "l"(src))
#define CPCOMMIT() asm volatile("cp.async.commit_group;" ::: "memory")
#define CPWAIT0()  asm volatile("cp.async.wait_group 0;" ::: "memory")
#define CPWAIT1()  asm volatile("cp.async.wait_group 1;" ::: "memory")

#define LDSM4(r, addr) \
    asm volatile("ldmatrix.sync.aligned.m8n8.x4.shared.b16 {%0,%1,%2,%3}, [%4];" \
        : "=r"((r)[0]), "=r"((r)[1]), "=r"((r)[2]), "=r"((r)[3]) : "r"(addr))

#define MMA_BF16(d, a, b) \
    asm volatile("mma.sync.aligned.m16n8k16.row.col.f32.bf16.bf16.f32 " \
        "{%0,%1,%2,%3}, {%4,%5,%6,%7}, {%8,%9}, {%0,%1,%2,%3};" \
        : "+f"((d)[0]), "+f"((d)[1]), "+f"((d)[2]), "+f"((d)[3]) \
        : "r"((a)[0]), "r"((a)[1]), "r"((a)[2]), "r"((a)[3]), \
          "r"((b)[0]), "r"((b)[1]))

// ====================================================================
// K0: WT[n][k] = bf16(W[k][n]).  grid (16,16,2): z selects W1a / W2.
// ====================================================================
__global__ void k_wt2(const float* __restrict__ W1, const float* __restrict__ W2) {
    __shared__ float t[32][33];
    const float* W = (blockIdx.z == 0) ? W1 : W2;
    __nv_bfloat16* WT = (blockIdx.z == 0) ? g_WT1b : g_WT2b;
    int bx = blockIdx.x * 32, by = blockIdx.y * 32;
    int x = threadIdx.x, y = threadIdx.y;         // (32, 8)
#pragma unroll
    for (int i = 0; i < 32; i += 8)
        t[y + i][x] = W[(size_t)(by + y + i) * HH + bx + x];
    __syncthreads();
#pragma unroll
    for (int i = 0; i < 32; i += 8)
        WT[(size_t)(bx + y + i) * HH + by + x] = __float2bfloat16(t[x][y + i]);
}

// ====================================================================
// K1a: partial c over 256-wide y-slice, 8 accumulator chains.
// grid (64, 10), 512 threads.  K1b: c = b1 + sum of 10 partials.
// ====================================================================
__global__ void k_compute_c_part(const float* __restrict__ io,
                                 const float* __restrict__ W1) {
    int b = blockIdx.x, s = blockIdx.y;
    int h = threadIdx.x;
    const float* e = io + b * YY + s * 256;
    const float* w = W1 + (size_t)(XX + s * 256) * HH + h;
    float a0 = 0.f, a1 = 0.f, a2 = 0.f, a3 = 0.f;
    float a4 = 0.f, a5 = 0.f, a6 = 0.f, a7 = 0.f;
#pragma unroll 4
    for (int y = 0; y < 256; y += 8) {
        a0 = fmaf(e[y],     w[(size_t)(y)     * HH], a0);
        a1 = fmaf(e[y + 1], w[(size_t)(y + 1) * HH], a1);
        a2 = fmaf(e[y + 2], w[(size_t)(y + 2) * HH], a2);
        a3 = fmaf(e[y + 3], w[(size_t)(y + 3) * HH], a3);
        a4 = fmaf(e[y + 4], w[(size_t)(y + 4) * HH], a4);
        a5 = fmaf(e[y + 5], w[(size_t)(y + 5) * HH], a5);
        a6 = fmaf(e[y + 6], w[(size_t)(y + 6) * HH], a6);
        a7 = fmaf(e[y + 7], w[(size_t)(y + 7) * HH], a7);
    }
    g_cpart[s][b * HH + h] = ((a0 + a1) + (a2 + a3)) + ((a4 + a5) + (a6 + a7));
}
__global__ void k_compute_c_red(const float* __restrict__ b1) {
    int i = blockIdx.x * 512 + threadIdx.x;
    float s = b1[threadIdx.x];
#pragma unroll
    for (int p = 0; p < 10; p++) s += g_cpart[p][i];
    g_c[i] = s;
}

// ====================================================================
// bf16 mma.sync GEMM: block 128(M)x128(N), BK=32, 256 thr = 8 warps,
// warp tile 64x32, 3-stage cp.async pipeline (wait_group 1), 2 CTA/SM.
// Fragment double-buffering: ks=0 AND ks=1 frags loaded before any MMA
// (16-MMA dependency distance behind every ldmatrix).
// Smem rows 40 shorts (80B): row*20 mod 32 covers all banks.
// MODE 0: A = ps f32 (LDG+cvt+STS); out H1b = bf16(relu(D + c[seg])).
// MODE 1: A = H1b bf16 (cp.async); out g_part[bx] per-row partial.
// ====================================================================
#define ABYT 10240                    // 128*40*2 per stage (A or B)
#define STG  20480                    // stage stride (A+B)
#define SM_DYN (3 * STG)              // 61440

template <int MODE>
__global__ __launch_bounds__(256, 2)
void k_gemm(const float* __restrict__ Af,          // MODE 0 source (f32)
            const __nv_bfloat16* __restrict__ Ab,  // MODE 1 source (bf16)
            const __nv_bfloat16* __restrict__ WT,  // [n][k] bf16
            const int*   __restrict__ seg,         // MODE 0
            const float* __restrict__ b2,          // MODE 1
            const float* __restrict__ W3) {        // MODE 1
    extern __shared__ char sm[];
    __shared__ float s_red[4][128];
    __shared__ float s_b2[128], s_w3[128];

    const int tid  = threadIdx.x;
    const int wid  = tid >> 5, lane = tid & 31;
    const int g    = lane >> 2, tg = lane & 3;
    const int wm   = (wid >> 2) * 64;             // 0 / 64
    const int wn   = (wid & 3) * 32;              // 0..96
    const int row0 = blockIdx.y * 128;
    const int col0 = blockIdx.x * 128;
    const uint32_t sb = smem_u32(sm);

    if (MODE == 1 && tid < 128) { s_b2[tid] = b2[col0 + tid]; s_w3[tid] = W3[col0 + tid]; }

    float acc[4][4][4];
#pragma unroll
    for (int mi = 0; mi < 4; mi++)
#pragma unroll
        for (int ni = 0; ni < 4; ni++)
#pragma unroll
            for (int q = 0; q < 4; q++) acc[mi][ni][q] = 0.f;

    // ldmatrix lane address components
    const int a_row = (lane & 7) + ((lane >> 3) & 1) * 8;
    const int a_kh  = (lane >> 4) & 1;
    const int b_n   = (lane & 7) + ((lane >> 4) & 1) * 8;
    const int b_kh  = (lane >> 3) & 1;

    float4 pa[4];                                  // MODE 0 A staging (one stage ahead)

#define CP_ISSUE(kt, st) do { \
    const uint32_t bbp = sb + (st) * STG + ABYT; \
    _Pragma("unroll") \
    for (int j = 0; j < 2; j++) { \
        int c = tid + j * 256, n = c >> 2, part = c & 3; \
        CP16(bbp + n * 80 + part * 16, \
             WT + (size_t)(col0 + n) * 512 + (kt) * 32 + part * 8); \
    } \
    if (MODE == 1) { \
        const uint32_t abp = sb + (st) * STG; \
        _Pragma("unroll") \
        for (int j = 0; j < 2; j++) { \
            int c = tid + j * 256, r = c >> 2, part = c & 3; \
            CP16(abp + r * 80 + part * 16, \
                 Ab + (size_t)(row0 + r) * 512 + (kt) * 32 + part * 8); \
        } \
    } } while (0)

#define A_LDG(kt) do { \
    _Pragma("unroll") \
    for (int j = 0; j < 4; j++) { \
        int c = tid + j * 256, r = c >> 3, part = c & 7; \
        pa[j] = *(const float4*)(Af + (size_t)(row0 + r) * 512 + (kt) * 32 + part * 4); \
    } } while (0)

#define A_STS(st) do { \
    const uint32_t abp = sb + (st) * STG; \
    _Pragma("unroll") \
    for (int j = 0; j < 4; j++) { \
        int c = tid + j * 256, r = c >> 3, part = c & 7; \
        __nv_bfloat162 lo = __float22bfloat162_rn(make_float2(pa[j].x, pa[j].y)); \
        __nv_bfloat162 hi = __float22bfloat162_rn(make_float2(pa[j].z, pa[j].w)); \
        uint32_t ulo = *(uint32_t*)&lo, uhi = *(uint32_t*)&hi; \
        asm volatile("st.shared.v2.u32 [%0], {%1, %2};" \
            :: "r"(abp + r * 80 + part * 8), "r"(ulo), "r"(uhi)); \
    } } while (0)

    // ---- prologue: stages 0 and 1 in flight ----
    CP_ISSUE(0, 0); CPCOMMIT();
    CP_ISSUE(1, 1); CPCOMMIT();
    if (MODE == 0) {
        A_LDG(0); A_STS(0);
        A_LDG(1); A_STS(1);
        A_LDG(2);                       // pa holds stage-2 data
    }

    for (int kt = 0; kt < 16; kt++) {
        const int buf = kt % 3;
        const int nxt = (kt + 2) % 3;
        if (kt >= 14) { CPWAIT0(); } else { CPWAIT1(); }   // stage kt arrived
        __syncthreads();
        if (kt < 14) {
            CP_ISSUE(kt + 2, nxt);
            CPCOMMIT();
            if (MODE == 0) A_STS(nxt);  // consumes pa (refilled after MMAs)
        }
        const uint32_t ab = sb + buf * STG;
        const uint32_t bb = ab + ABYT;

        // ---- load ALL fragments for both k-steps, then MMA ----
        uint32_t af[2][4][4], bf[2][4][2];
#pragma unroll
        for (int ks = 0; ks < 2; ks++) {
#pragma unroll
            for (int mi = 0; mi < 4; mi++)
                LDSM4(af[ks][mi], ab + (wm + mi * 16 + a_row) * 80 + ks * 32 + a_kh * 16);
#pragma unroll
            for (int p = 0; p < 2; p++) {
                uint32_t r4[4];
                LDSM4(r4, bb + (wn + p * 16 + b_n) * 80 + ks * 32 + b_kh * 16);
                bf[ks][2 * p][0] = r4[0]; bf[ks][2 * p][1] = r4[1];
                bf[ks][2 * p + 1][0] = r4[2]; bf[ks][2 * p + 1][1] = r4[3];
            }
        }
#pragma unroll
        for (int ks = 0; ks < 2; ks++)
#pragma unroll
            for (int mi = 0; mi < 4; mi++)
#pragma unroll
                for (int ni = 0; ni < 4; ni++)
                    MMA_BF16(acc[mi][ni], af[ks][mi], bf[ks][ni]);

        if (MODE == 0 && kt < 13) A_LDG(kt + 3);   // refill pa (pa dead above)
    }

    // -------- epilogue --------
    if (MODE == 0) {
#pragma unroll
        for (int mi = 0; mi < 4; mi++) {
#pragma unroll
            for (int h = 0; h < 2; h++) {
                int r = row0 + wm + mi * 16 + g + h * 8;
                const float* crow = g_c + (size_t)__ldg(seg + r) * 512;
                __nv_bfloat16* orow = g_H1b + (size_t)r * 512;
#pragma unroll
                for (int ni = 0; ni < 4; ni++) {
                    int col = col0 + wn + ni * 8 + 2 * tg;
                    float x0 = fmaxf(acc[mi][ni][h * 2 + 0] + crow[col], 0.f);
                    float x1 = fmaxf(acc[mi][ni][h * 2 + 1] + crow[col + 1], 0.f);
                    __nv_bfloat162 o = __float22bfloat162_rn(make_float2(x0, x1));
                    *(__nv_bfloat162*)(orow + col) = o;
                }
            }
        }
    } else {
        float rp[4][2];
#pragma unroll
        for (int mi = 0; mi < 4; mi++) {
#pragma unroll
            for (int h = 0; h < 2; h++) {
                float s = 0.f;
#pragma unroll
                for (int ni = 0; ni < 4; ni++) {
                    int cl = wn + ni * 8 + 2 * tg;
                    s = fmaf(fmaxf(acc[mi][ni][h * 2 + 0] + s_b2[cl], 0.f), s_w3[cl], s);
                    s = fmaf(fmaxf(acc[mi][ni][h * 2 + 1] + s_b2[cl + 1], 0.f), s_w3[cl + 1], s);
                }
                s += __shfl_xor_sync(0xffffffffu, s, 1);
                s += __shfl_xor_sync(0xffffffffu, s, 2);
                rp[mi][h] = s;
            }
        }
        __syncthreads();
        if (tg == 0) {
#pragma unroll
            for (int mi = 0; mi < 4; mi++)
#pragma unroll
                for (int h = 0; h < 2; h++)
                    s_red[wid & 3][wm + mi * 16 + g + h * 8] = rp[mi][h];
        }
        __syncthreads();
        if (tid < 128) {
            float v = (s_red[0][tid] + s_red[1][tid]) + (s_red[2][tid] + s_red[3][tid]);
            g_part[(size_t)blockIdx.x * TT + row0 + tid] = v;
        }
    }
#undef CP_ISSUE
#undef A_LDG
#undef A_STS
}

// ====================================================================
// K5: per-segment softmax + pooling.  64 blocks x 512 threads.
// Pass 1 builds logits from the 4 g_part slices (logit_red folded in;
// passes use the same tid striping, so threads read only their own writes).
// ====================================================================
__global__ void k_seg_pool(const int* __restrict__ seg,
                           const float* __restrict__ ps,
                           const float* __restrict__ b3) {
    __shared__ float sbuf[512];
    __shared__ float s_mx, s_dn;
    const int b   = blockIdx.x;
    const int tid = threadIdx.x;

    int lo = 0, hi = TT;
    while (lo < hi) { int mid = (lo + hi) >> 1; if (seg[mid] < b) lo = mid + 1; else hi = mid; }
    const int start = lo;
    hi = TT;
    while (lo < hi) { int mid = (lo + hi) >> 1; if (seg[mid] < b + 1) lo = mid + 1; else hi = mid; }
    const int end = lo;

    const float b3v = b3[0];
    float m = -1e30f;
    for (int t = start + tid; t < end; t += 512) {
        float l = ((g_part[t] + g_part[TT + t])
                 + (g_part[2 * TT + t] + g_part[3 * TT + t])) + b3v;
        g_logits[t] = l;
        m = fmaxf(m, l);
    }
    sbuf[tid] = m; __syncthreads();
    for (int s = 256; s > 0; s >>= 1) {
        if (tid < s) sbuf[tid] = fmaxf(sbuf[tid], sbuf[tid + s]);
        __syncthreads();
    }
    if (tid == 0) s_mx = sbuf[0];
    __syncthreads();
    const float mx = s_mx;

    float sm = 0.f;
    for (int t = start + tid; t < end; t += 512) sm += expf(g_logits[t] - mx);
    __syncthreads();
    sbuf[tid] = sm; __syncthreads();
    for (int s = 256; s > 0; s >>= 1) {
        if (tid < s) sbuf[tid] += sbuf[tid + s];
        __syncthreads();
    }
    if (tid == 0) s_dn = sbuf[0];
    __syncthreads();
    const float inv = (end > start) ? 1.f / s_dn : 0.f;

    float a0 = 0.f, a1 = 0.f, a2 = 0.f, a3 = 0.f;
    float a4 = 0.f, a5 = 0.f, a6 = 0.f, a7 = 0.f;
    for (int c0 = start; c0 < end; c0 += 512) {
        int nt = min(512, end - c0);
        __syncthreads();
        if (tid < nt) sbuf[tid] = expf(g_logits[c0 + tid] - mx);
        __syncthreads();
        const float* prow = ps + (size_t)c0 * XX + tid;
        int i = 0;
        for (; i + 7 < nt; i += 8) {
            a0 = fmaf(sbuf[i],     prow[(size_t)(i)     * XX], a0);
            a1 = fmaf(sbuf[i + 1], prow[(size_t)(i + 1) * XX], a1);
            a2 = fmaf(sbuf[i + 2], prow[(size_t)(i + 2) * XX], a2);
            a3 = fmaf(sbuf[i + 3], prow[(size_t)(i + 3) * XX], a3);
            a4 = fmaf(sbuf[i + 4], prow[(size_t)(i + 4) * XX], a4);
            a5 = fmaf(sbuf[i + 5], prow[(size_t)(i + 5) * XX], a5);
            a6 = fmaf(sbuf[i + 6], prow[(size_t)(i + 6) * XX], a6);
            a7 = fmaf(sbuf[i + 7], prow[(size_t)(i + 7) * XX], a7);
        }
        for (; i < nt; i++)
            a0 = fmaf(sbuf[i], prow[(size_t)i * XX], a0);
    }
    g_pooled[(size_t)b * XX + tid] =
        (((a0 + a1) + (a2 + a3)) + ((a4 + a5) + (a6 + a7))) * inv;
}

// ====================================================================
// K6: out[b] = relu(pooled[b] @ Wf1 + bf1) @ Wf2 + bf2   (exact fp32)
// ====================================================================
__global__ void k_final(const float* __restrict__ Wf1,
                        const float* __restrict__ bf1,
                        const float* __restrict__ Wf2,
                        const float* __restrict__ bf2,
                        float* __restrict__ out) {
    __shared__ float p[512];
    __shared__ float hf[512];
    const int b = blockIdx.x;
    const int tid = threadIdx.x;

    p[tid] = g_pooled[b * XX + tid];
    __syncthreads();

    float acc = bf1[tid];
#pragma unroll 4
    for (int k = 0; k < 512; k++)
        acc = fmaf(p[k], Wf1[(size_t)k * 512 + tid], acc);
    hf[tid] = fmaxf(acc, 0.f);
    __syncthreads();

    float v0 = hf[tid] * Wf2[tid * 2 + 0];
    float v1 = hf[tid] * Wf2[tid * 2 + 1];
    __syncthreads();
    p[tid] = v0; __syncthreads();
    for (int s = 256; s > 0; s >>= 1) { if (tid < s) p[tid] += p[tid + s]; __syncthreads(); }
    if (tid == 0) out[b * 2 + 0] = p[0] + bf2[0];
    __syncthreads();
    p[tid] = v1; __syncthreads();
    for (int s = 256; s > 0; s >>= 1) { if (tid < s) p[tid] += p[tid + s]; __syncthreads(); }
    if (tid == 0) out[b * 2 + 1] = p[0] + bf2[1];
}

// ====================================================================
extern "C" void kernel_launch(void* const* d_in, const int* in_sizes, int n_in,
                              void* d_out, int out_size) {
    const float* ps  = (const float*)d_in[0];
    const float* io  = (const float*)d_in[1];
    const int*   seg = (const int*)  d_in[2];
    const float* W1  = (const float*)d_in[3];
    const float* b1  = (const float*)d_in[4];
    const float* W2  = (const float*)d_in[5];
    const float* b2  = (const float*)d_in[6];
    const float* W3  = (const float*)d_in[7];
    const float* b3  = (const float*)d_in[8];
    const float* Wf1 = (const float*)d_in[9];
    const float* bf1 = (const float*)d_in[10];
    const float* Wf2 = (const float*)d_in[11];
    const float* bf2 = (const float*)d_in[12];
    float* out = (float*)d_out;

    __nv_bfloat16 *H1b, *WT1b, *WT2b;
    cudaGetSymbolAddress((void**)&H1b,  g_H1b);
    cudaGetSymbolAddress((void**)&WT1b, g_WT1b);
    cudaGetSymbolAddress((void**)&WT2b, g_WT2b);

    cudaFuncSetAttribute(k_gemm<0>, cudaFuncAttributeMaxDynamicSharedMemorySize, SM_DYN);
    cudaFuncSetAttribute(k_gemm<1>, cudaFuncAttributeMaxDynamicSharedMemorySize, SM_DYN);

    k_wt2<<<dim3(16, 16, 2), dim3(32, 8)>>>(W1, W2);
    k_compute_c_part<<<dim3(BB, 10), 512>>>(io, W1);
    k_compute_c_red<<<BB, 512>>>(b1);

    // H1 = bf16(relu(ps @ W1a + c[seg]))
    k_gemm<0><<<dim3(4, 512), 256, SM_DYN>>>(ps, nullptr, WT1b, seg, nullptr, nullptr);
    // logit partials = relu(H1 @ W2 + b2) . W3 per 128-col block
    k_gemm<1><<<dim3(4, 512), 256, SM_DYN>>>(nullptr, H1b, WT2b, nullptr, b2, W3);

    k_seg_pool<<<BB, 512>>>(seg, ps, b3);
    k_final<<<BB, 512>>>(Wf1, bf1, Wf2, bf2, out);
}

// round 17
// speedup vs baseline: 1.3996x; 1.2622x over previous
#include <cuda_runtime.h>
#include <cuda_bf16.h>
#include <math.h>
#include <stdint.h>

#define TT 65536
#define BB 64
#define XX 512
#define HH 512
#define YY 2560

// -------- scratch (device globals; no allocation allowed) --------
__device__ float g_cpart[10][BB * HH];
__device__ float g_c[BB * HH];
__device__ __nv_bfloat16 g_H1b[(size_t)TT * HH];
__device__ __nv_bfloat16 g_WT1b[HH * HH];   // W1[:512] transposed [n][k], bf16
__device__ __nv_bfloat16 g_WT2b[HH * HH];   // W2 transposed [n][k], bf16
__device__ float g_part[4 * TT];
__device__ float g_ppart[4][BB * XX];       // pooled partials per token-chunk
__device__ float g_pooled_unused[1];

// ==================== PTX helpers ====================
__device__ __forceinline__ uint32_t smem_u32(const void* p) {
    uint32_t a;
    asm("{ .reg .u64 t; cvta.to.shared.u64 t, %1; cvt.u32.u64 %0, t; }"
        : "=r"(a) : "l"(p));
    return a;
}
#define CP16(dst, src) \
    asm volatile("cp.async.cg.shared.global [%0], [%1], 16;" :: "r"(dst), "l"(src))
#define CPCOMMIT() asm volatile("cp.async.commit_group;" ::: "memory")
#define CPWAIT0()  asm volatile("cp.async.wait_group 0;" ::: "memory")
#define CPWAIT1()  asm volatile("cp.async.wait_group 1;" ::: "memory")

#define LDSM4(r, addr) \
    asm volatile("ldmatrix.sync.aligned.m8n8.x4.shared.b16 {%0,%1,%2,%3}, [%4];" \
        : "=r"((r)[0]), "=r"((r)[1]), "=r"((r)[2]), "=r"((r)[3]) : "r"(addr))

#define MMA_BF16(d, a, b) \
    asm volatile("mma.sync.aligned.m16n8k16.row.col.f32.bf16.bf16.f32 " \
        "{%0,%1,%2,%3}, {%4,%5,%6,%7}, {%8,%9}, {%0,%1,%2,%3};" \
        : "+f"((d)[0]), "+f"((d)[1]), "+f"((d)[2]), "+f"((d)[3]) \
        : "r"((a)[0]), "r"((a)[1]), "r"((a)[2]), "r"((a)[3]), \
          "r"((b)[0]), "r"((b)[1]))

// ====================================================================
// K0: WT[n][k] = bf16(W[k][n]).  grid (16,16,2): z selects W1a / W2.
// ====================================================================
__global__ void k_wt2(const float* __restrict__ W1, const float* __restrict__ W2) {
    __shared__ float t[32][33];
    const float* W = (blockIdx.z == 0) ? W1 : W2;
    __nv_bfloat16* WT = (blockIdx.z == 0) ? g_WT1b : g_WT2b;
    int bx = blockIdx.x * 32, by = blockIdx.y * 32;
    int x = threadIdx.x, y = threadIdx.y;         // (32, 8)
#pragma unroll
    for (int i = 0; i < 32; i += 8)
        t[y + i][x] = W[(size_t)(by + y + i) * HH + bx + x];
    __syncthreads();
#pragma unroll
    for (int i = 0; i < 32; i += 8)
        WT[(size_t)(bx + y + i) * HH + by + x] = __float2bfloat16(t[x][y + i]);
}

// ====================================================================
// K1a: partial c over 256-wide y-slice, 8 accumulator chains.
// grid (64, 10), 512 threads.  K1b: c = b1 + sum of 10 partials.
// ====================================================================
__global__ void k_compute_c_part(const float* __restrict__ io,
                                 const float* __restrict__ W1) {
    int b = blockIdx.x, s = blockIdx.y;
    int h = threadIdx.x;
    const float* e = io + b * YY + s * 256;
    const float* w = W1 + (size_t)(XX + s * 256) * HH + h;
    float a0 = 0.f, a1 = 0.f, a2 = 0.f, a3 = 0.f;
    float a4 = 0.f, a5 = 0.f, a6 = 0.f, a7 = 0.f;
#pragma unroll 4
    for (int y = 0; y < 256; y += 8) {
        a0 = fmaf(e[y],     w[(size_t)(y)     * HH], a0);
        a1 = fmaf(e[y + 1], w[(size_t)(y + 1) * HH], a1);
        a2 = fmaf(e[y + 2], w[(size_t)(y + 2) * HH], a2);
        a3 = fmaf(e[y + 3], w[(size_t)(y + 3) * HH], a3);
        a4 = fmaf(e[y + 4], w[(size_t)(y + 4) * HH], a4);
        a5 = fmaf(e[y + 5], w[(size_t)(y + 5) * HH], a5);
        a6 = fmaf(e[y + 6], w[(size_t)(y + 6) * HH], a6);
        a7 = fmaf(e[y + 7], w[(size_t)(y + 7) * HH], a7);
    }
    g_cpart[s][b * HH + h] = ((a0 + a1) + (a2 + a3)) + ((a4 + a5) + (a6 + a7));
}
__global__ void k_compute_c_red(const float* __restrict__ b1) {
    int i = blockIdx.x * 512 + threadIdx.x;
    float s = b1[threadIdx.x];
#pragma unroll
    for (int p = 0; p < 10; p++) s += g_cpart[p][i];
    g_c[i] = s;
}

// ====================================================================
// bf16 mma.sync GEMM: block 128(M)x128(N), BK=32, 256 thr = 8 warps,
// warp tile 64x32, 3-stage cp.async pipeline (wait_group 1), 2 CTA/SM.
// Fragment double-buffering: ks=0 AND ks=1 frags loaded before any MMA.
// Smem rows 40 shorts (80B): row*20 mod 32 covers all banks.
// MODE 0: A = ps f32 (LDG+cvt+STS); out H1b = bf16(relu(D + c[seg])).
// MODE 1: A = H1b bf16 (cp.async); out g_part[bx] per-row partial.
// ====================================================================
#define ABYT 10240                    // 128*40*2 per stage (A or B)
#define STG  20480                    // stage stride (A+B)
#define SM_DYN (3 * STG)              // 61440

template <int MODE>
__global__ __launch_bounds__(256, 2)
void k_gemm(const float* __restrict__ Af,          // MODE 0 source (f32)
            const __nv_bfloat16* __restrict__ Ab,  // MODE 1 source (bf16)
            const __nv_bfloat16* __restrict__ WT,  // [n][k] bf16
            const int*   __restrict__ seg,         // MODE 0
            const float* __restrict__ b2,          // MODE 1
            const float* __restrict__ W3) {        // MODE 1
    extern __shared__ char sm[];
    __shared__ float s_red[4][128];
    __shared__ float s_b2[128], s_w3[128];

    const int tid  = threadIdx.x;
    const int wid  = tid >> 5, lane = tid & 31;
    const int g    = lane >> 2, tg = lane & 3;
    const int wm   = (wid >> 2) * 64;             // 0 / 64
    const int wn   = (wid & 3) * 32;              // 0..96
    const int row0 = blockIdx.y * 128;
    const int col0 = blockIdx.x * 128;
    const uint32_t sb = smem_u32(sm);

    if (MODE == 1 && tid < 128) { s_b2[tid] = b2[col0 + tid]; s_w3[tid] = W3[col0 + tid]; }

    float acc[4][4][4];
#pragma unroll
    for (int mi = 0; mi < 4; mi++)
#pragma unroll
        for (int ni = 0; ni < 4; ni++)
#pragma unroll
            for (int q = 0; q < 4; q++) acc[mi][ni][q] = 0.f;

    // ldmatrix lane address components
    const int a_row = (lane & 7) + ((lane >> 3) & 1) * 8;
    const int a_kh  = (lane >> 4) & 1;
    const int b_n   = (lane & 7) + ((lane >> 4) & 1) * 8;
    const int b_kh  = (lane >> 3) & 1;

    float4 pa[4];                                  // MODE 0 A staging (one stage ahead)

#define CP_ISSUE(kt, st) do { \
    const uint32_t bbp = sb + (st) * STG + ABYT; \
    _Pragma("unroll") \
    for (int j = 0; j < 2; j++) { \
        int c = tid + j * 256, n = c >> 2, part = c & 3; \
        CP16(bbp + n * 80 + part * 16, \
             WT + (size_t)(col0 + n) * 512 + (kt) * 32 + part * 8); \
    } \
    if (MODE == 1) { \
        const uint32_t abp = sb + (st) * STG; \
        _Pragma("unroll") \
        for (int j = 0; j < 2; j++) { \
            int c = tid + j * 256, r = c >> 2, part = c & 3; \
            CP16(abp + r * 80 + part * 16, \
                 Ab + (size_t)(row0 + r) * 512 + (kt) * 32 + part * 8); \
        } \
    } } while (0)

#define A_LDG(kt) do { \
    _Pragma("unroll") \
    for (int j = 0; j < 4; j++) { \
        int c = tid + j * 256, r = c >> 3, part = c & 7; \
        pa[j] = *(const float4*)(Af + (size_t)(row0 + r) * 512 + (kt) * 32 + part * 4); \
    } } while (0)

#define A_STS(st) do { \
    const uint32_t abp = sb + (st) * STG; \
    _Pragma("unroll") \
    for (int j = 0; j < 4; j++) { \
        int c = tid + j * 256, r = c >> 3, part = c & 7; \
        __nv_bfloat162 lo = __float22bfloat162_rn(make_float2(pa[j].x, pa[j].y)); \
        __nv_bfloat162 hi = __float22bfloat162_rn(make_float2(pa[j].z, pa[j].w)); \
        uint32_t ulo = *(uint32_t*)&lo, uhi = *(uint32_t*)&hi; \
        asm volatile("st.shared.v2.u32 [%0], {%1, %2};" \
            :: "r"(abp + r * 80 + part * 8), "r"(ulo), "r"(uhi)); \
    } } while (0)

    // ---- prologue: stages 0 and 1 in flight ----
    CP_ISSUE(0, 0); CPCOMMIT();
    CP_ISSUE(1, 1); CPCOMMIT();
    if (MODE == 0) {
        A_LDG(0); A_STS(0);
        A_LDG(1); A_STS(1);
        A_LDG(2);                       // pa holds stage-2 data
    }

    for (int kt = 0; kt < 16; kt++) {
        const int buf = kt % 3;
        const int nxt = (kt + 2) % 3;
        if (kt >= 14) { CPWAIT0(); } else { CPWAIT1(); }   // stage kt arrived
        __syncthreads();
        if (kt < 14) {
            CP_ISSUE(kt + 2, nxt);
            CPCOMMIT();
            if (MODE == 0) A_STS(nxt);  // consumes pa (refilled after MMAs)
        }
        const uint32_t ab = sb + buf * STG;
        const uint32_t bb = ab + ABYT;

        // ---- load ALL fragments for both k-steps, then MMA ----
        uint32_t af[2][4][4], bf[2][4][2];
#pragma unroll
        for (int ks = 0; ks < 2; ks++) {
#pragma unroll
            for (int mi = 0; mi < 4; mi++)
                LDSM4(af[ks][mi], ab + (wm + mi * 16 + a_row) * 80 + ks * 32 + a_kh * 16);
#pragma unroll
            for (int p = 0; p < 2; p++) {
                uint32_t r4[4];
                LDSM4(r4, bb + (wn + p * 16 + b_n) * 80 + ks * 32 + b_kh * 16);
                bf[ks][2 * p][0] = r4[0]; bf[ks][2 * p][1] = r4[1];
                bf[ks][2 * p + 1][0] = r4[2]; bf[ks][2 * p + 1][1] = r4[3];
            }
        }
#pragma unroll
        for (int ks = 0; ks < 2; ks++)
#pragma unroll
            for (int mi = 0; mi < 4; mi++)
#pragma unroll
                for (int ni = 0; ni < 4; ni++)
                    MMA_BF16(acc[mi][ni], af[ks][mi], bf[ks][ni]);

        if (MODE == 0 && kt < 13) A_LDG(kt + 3);   // refill pa (pa dead above)
    }

    // -------- epilogue --------
    if (MODE == 0) {
#pragma unroll
        for (int mi = 0; mi < 4; mi++) {
#pragma unroll
            for (int h = 0; h < 2; h++) {
                int r = row0 + wm + mi * 16 + g + h * 8;
                const float* crow = g_c + (size_t)__ldg(seg + r) * 512;
                __nv_bfloat16* orow = g_H1b + (size_t)r * 512;
#pragma unroll
                for (int ni = 0; ni < 4; ni++) {
                    int col = col0 + wn + ni * 8 + 2 * tg;
                    float x0 = fmaxf(acc[mi][ni][h * 2 + 0] + crow[col], 0.f);
                    float x1 = fmaxf(acc[mi][ni][h * 2 + 1] + crow[col + 1], 0.f);
                    __nv_bfloat162 o = __float22bfloat162_rn(make_float2(x0, x1));
                    *(__nv_bfloat162*)(orow + col) = o;
                }
            }
        }
    } else {
        float rp[4][2];
#pragma unroll
        for (int mi = 0; mi < 4; mi++) {
#pragma unroll
            for (int h = 0; h < 2; h++) {
                float s = 0.f;
#pragma unroll
                for (int ni = 0; ni < 4; ni++) {
                    int cl = wn + ni * 8 + 2 * tg;
                    s = fmaf(fmaxf(acc[mi][ni][h * 2 + 0] + s_b2[cl], 0.f), s_w3[cl], s);
                    s = fmaf(fmaxf(acc[mi][ni][h * 2 + 1] + s_b2[cl + 1], 0.f), s_w3[cl + 1], s);
                }
                s += __shfl_xor_sync(0xffffffffu, s, 1);
                s += __shfl_xor_sync(0xffffffffu, s, 2);
                rp[mi][h] = s;
            }
        }
        __syncthreads();
        if (tg == 0) {
#pragma unroll
            for (int mi = 0; mi < 4; mi++)
#pragma unroll
                for (int h = 0; h < 2; h++)
                    s_red[wid & 3][wm + mi * 16 + g + h * 8] = rp[mi][h];
        }
        __syncthreads();
        if (tid < 128) {
            float v = (s_red[0][tid] + s_red[1][tid]) + (s_red[2][tid] + s_red[3][tid]);
            g_part[(size_t)blockIdx.x * TT + row0 + tid] = v;
        }
    }
#undef CP_ISSUE
#undef A_LDG
#undef A_STS
}

// ====================================================================
// K5: per-segment softmax + pooling, token-chunk parallel.
// grid (64, 4) x 512 threads.  Block (b,q):
//   - recomputes segment max & denom from g_part slices (identical loop
//     order in all 4 blocks -> bit-identical mx/denom, deterministic)
//   - pools tokens [cs, ce) (quarter q of the segment) into g_ppart[q].
// g_logits eliminated.
// ====================================================================
__device__ __forceinline__ float logit_at(int t, float b3v) {
    return ((g_part[t] + g_part[TT + t])
          + (g_part[2 * TT + t] + g_part[3 * TT + t])) + b3v;
}

__global__ void k_seg_pool_part(const int* __restrict__ seg,
                                const float* __restrict__ ps,
                                const float* __restrict__ b3) {
    __shared__ float sbuf[512];
    __shared__ float s_mx, s_dn;
    const int b   = blockIdx.x;
    const int q   = blockIdx.y;
    const int tid = threadIdx.x;

    int lo = 0, hi = TT;
    while (lo < hi) { int mid = (lo + hi) >> 1; if (seg[mid] < b) lo = mid + 1; else hi = mid; }
    const int start = lo;
    hi = TT;
    while (lo < hi) { int mid = (lo + hi) >> 1; if (seg[mid] < b + 1) lo = mid + 1; else hi = mid; }
    const int end = lo;
    const int len = end - start;

    const float b3v = b3[0];

    // pass 1: full-segment max (identical in all 4 q-blocks)
    float m = -1e30f;
    for (int t = start + tid; t < end; t += 512) m = fmaxf(m, logit_at(t, b3v));
    sbuf[tid] = m; __syncthreads();
    for (int s = 256; s > 0; s >>= 1) {
        if (tid < s) sbuf[tid] = fmaxf(sbuf[tid], sbuf[tid + s]);
        __syncthreads();
    }
    if (tid == 0) s_mx = sbuf[0];
    __syncthreads();
    const float mx = s_mx;

    // pass 2: full-segment denom (identical in all 4 q-blocks)
    float sm = 0.f;
    for (int t = start + tid; t < end; t += 512) sm += expf(logit_at(t, b3v) - mx);
    __syncthreads();
    sbuf[tid] = sm; __syncthreads();
    for (int s = 256; s > 0; s >>= 1) {
        if (tid < s) sbuf[tid] += sbuf[tid + s];
        __syncthreads();
    }
    if (tid == 0) s_dn = sbuf[0];
    __syncthreads();
    const float inv = (len > 0) ? 1.f / s_dn : 0.f;

    // pass 3: pool chunk q's tokens only
    const int cs = start + (int)(((long long)len * q) >> 2);
    const int ce = start + (int)(((long long)len * (q + 1)) >> 2);

    float a0 = 0.f, a1 = 0.f, a2 = 0.f, a3 = 0.f;
    float a4 = 0.f, a5 = 0.f, a6 = 0.f, a7 = 0.f;
    for (int c0 = cs; c0 < ce; c0 += 512) {
        int nt = min(512, ce - c0);
        __syncthreads();
        if (tid < nt) sbuf[tid] = expf(logit_at(c0 + tid, b3v) - mx);
        __syncthreads();
        const float* prow = ps + (size_t)c0 * XX + tid;
        int i = 0;
        for (; i + 7 < nt; i += 8) {
            a0 = fmaf(sbuf[i],     prow[(size_t)(i)     * XX], a0);
            a1 = fmaf(sbuf[i + 1], prow[(size_t)(i + 1) * XX], a1);
            a2 = fmaf(sbuf[i + 2], prow[(size_t)(i + 2) * XX], a2);
            a3 = fmaf(sbuf[i + 3], prow[(size_t)(i + 3) * XX], a3);
            a4 = fmaf(sbuf[i + 4], prow[(size_t)(i + 4) * XX], a4);
            a5 = fmaf(sbuf[i + 5], prow[(size_t)(i + 5) * XX], a5);
            a6 = fmaf(sbuf[i + 6], prow[(size_t)(i + 6) * XX], a6);
            a7 = fmaf(sbuf[i + 7], prow[(size_t)(i + 7) * XX], a7);
        }
        for (; i < nt; i++)
            a0 = fmaf(sbuf[i], prow[(size_t)i * XX], a0);
    }
    g_ppart[q][(size_t)b * XX + tid] =
        (((a0 + a1) + (a2 + a3)) + ((a4 + a5) + (a6 + a7))) * inv;
}

// ====================================================================
// K6: out[b] = relu(pooled[b] @ Wf1 + bf1) @ Wf2 + bf2   (exact fp32)
// pooled = sum of the 4 token-chunk partials.
// ====================================================================
__global__ void k_final(const float* __restrict__ Wf1,
                        const float* __restrict__ bf1,
                        const float* __restrict__ Wf2,
                        const float* __restrict__ bf2,
                        float* __restrict__ out) {
    __shared__ float p[512];
    __shared__ float hf[512];
    const int b = blockIdx.x;
    const int tid = threadIdx.x;

    size_t idx = (size_t)b * XX + tid;
    p[tid] = (g_ppart[0][idx] + g_ppart[1][idx])
           + (g_ppart[2][idx] + g_ppart[3][idx]);
    __syncthreads();

    float acc = bf1[tid];
#pragma unroll 4
    for (int k = 0; k < 512; k++)
        acc = fmaf(p[k], Wf1[(size_t)k * 512 + tid], acc);
    hf[tid] = fmaxf(acc, 0.f);
    __syncthreads();

    float v0 = hf[tid] * Wf2[tid * 2 + 0];
    float v1 = hf[tid] * Wf2[tid * 2 + 1];
    __syncthreads();
    p[tid] = v0; __syncthreads();
    for (int s = 256; s > 0; s >>= 1) { if (tid < s) p[tid] += p[tid + s]; __syncthreads(); }
    if (tid == 0) out[b * 2 + 0] = p[0] + bf2[0];
    __syncthreads();
    p[tid] = v1; __syncthreads();
    for (int s = 256; s > 0; s >>= 1) { if (tid < s) p[tid] += p[tid + s]; __syncthreads(); }
    if (tid == 0) out[b * 2 + 1] = p[0] + bf2[1];
}

// ====================================================================
extern "C" void kernel_launch(void* const* d_in, const int* in_sizes, int n_in,
                              void* d_out, int out_size) {
    const float* ps  = (const float*)d_in[0];
    const float* io  = (const float*)d_in[1];
    const int*   seg = (const int*)  d_in[2];
    const float* W1  = (const float*)d_in[3];
    const float* b1  = (const float*)d_in[4];
    const float* W2  = (const float*)d_in[5];
    const float* b2  = (const float*)d_in[6];
    const float* W3  = (const float*)d_in[7];
    const float* b3  = (const float*)d_in[8];
    const float* Wf1 = (const float*)d_in[9];
    const float* bf1 = (const float*)d_in[10];
    const float* Wf2 = (const float*)d_in[11];
    const float* bf2 = (const float*)d_in[12];
    float* out = (float*)d_out;

    __nv_bfloat16 *H1b, *WT1b, *WT2b;
    cudaGetSymbolAddress((void**)&H1b,  g_H1b);
    cudaGetSymbolAddress((void**)&WT1b, g_WT1b);
    cudaGetSymbolAddress((void**)&WT2b, g_WT2b);

    cudaFuncSetAttribute(k_gemm<0>, cudaFuncAttributeMaxDynamicSharedMemorySize, SM_DYN);
    cudaFuncSetAttribute(k_gemm<1>, cudaFuncAttributeMaxDynamicSharedMemorySize, SM_DYN);

    k_wt2<<<dim3(16, 16, 2), dim3(32, 8)>>>(W1, W2);
    k_compute_c_part<<<dim3(BB, 10), 512>>>(io, W1);
    k_compute_c_red<<<BB, 512>>>(b1);

    // H1 = bf16(relu(ps @ W1a + c[seg]))
    k_gemm<0><<<dim3(4, 512), 256, SM_DYN>>>(ps, nullptr, WT1b, seg, nullptr, nullptr);
    // logit partials = relu(H1 @ W2 + b2) . W3 per 128-col block
    k_gemm<1><<<dim3(4, 512), 256, SM_DYN>>>(nullptr, H1b, WT2b, nullptr, b2, W3);

    // segment softmax + pooling, 4 token-chunks per segment
    k_seg_pool_part<<<dim3(BB, 4), 512>>>(seg, ps, b3);
    k_final<<<BB, 512>>>(Wf1, bf1, Wf2, bf2, out);
}